// round 15
// baseline (speedup 1.0000x reference)
#include <cuda_runtime.h>
#include <cuda_bf16.h>
#include <math.h>
#include <stdint.h>

#define NPTS 128
#define NTHR 128

// ---- smem byte offsets (all swizzled, zero padding) ----
#define WD1H 0        // 64 rows x 32 halves = 4096
#define WD1L 4096
#define WD2H 8192     // 64 x 64 = 8192
#define WD2L 16384
#define WD3H 24576    // 16 x 64 = 2048
#define WD3L 26624
#define WC1H 28672    // 64 x 16 = 2048
#define WC1L 30720
#define WC2H 32768
#define WC2L 40960
#define WC3H 49152
#define WC3L 57344
#define WHDH 65536    // head hi: rows 0..2 used; rows 3..7 overlap lo (garbage OK)
#define WHDL 65920    // = WHDH + 384; union = 1408 B
#define BIASO 66944   // floats, 1376 B
#define ACTO  68320   // 4 warps x 32 rows x 16 words x 4B = 8192 (16B aligned)
#define SMEMB 76512
#define DB1 0
#define DB2 64
#define DB3 128
#define CB1 144
#define CB2 208
#define CB3 272
#define HB  336

__device__ constexpr int RESV[16] = {16,20,25,32,40,50,64,80,101,128,161,203,256,322,406,512};

// pair-packed dense tables (levels 0..4)
#define DTOT 124489
__device__ float4 g_dense[DTOT];
__device__ constexpr int DOFF[5] = {0, 4096, 12096, 27721, 60489};

__global__ void __launch_bounds__(256) prep_dense(const float* __restrict__ gtab)
{
    int i = blockIdx.x * 256 + threadIdx.x;
    if (i >= DTOT) return;
    int l, off, sz;
    if      (i < 4096)  { l=0; off=0;     sz=4096;  }
    else if (i < 12096) { l=1; off=4096;  sz=8000;  }
    else if (i < 27721) { l=2; off=12096; sz=15625; }
    else if (i < 60489) { l=3; off=27721; sz=32768; }
    else                { l=4; off=60489; sz=64000; }
    int j = i - off;
    const float2* tab = (const float2*)gtab + ((size_t)l << 16);
    float2 a = tab[j];
    float2 b = tab[j + 1 < sz ? j + 1 : j];
    g_dense[i] = make_float4(a.x, a.y, b.x, b.y);
}

__device__ __forceinline__ uint32_t pk(float lo, float hi){
    uint32_t r; asm("cvt.rn.bf16x2.f32 %0, %1, %2;" : "=r"(r) : "f"(hi), "f"(lo)); return r;
}
__device__ __forceinline__ float blo(uint32_t v){ return __uint_as_float(v << 16); }
__device__ __forceinline__ float bhi(uint32_t v){ return __uint_as_float(v & 0xFFFF0000u); }

__device__ __forceinline__ void mmab(float* c, const uint32_t* a, uint32_t b0, uint32_t b1){
    asm volatile("mma.sync.aligned.m16n8k16.row.col.f32.bf16.bf16.f32 "
        "{%0,%1,%2,%3}, {%4,%5,%6,%7}, {%8,%9}, {%0,%1,%2,%3};"
        : "+f"(c[0]), "+f"(c[1]), "+f"(c[2]), "+f"(c[3])
        : "r"(a[0]), "r"(a[1]), "r"(a[2]), "r"(a[3]), "r"(b0), "r"(b1));
}

// swizzle helpers: k' index within a row of KW halves
__device__ __forceinline__ int swz64(int n, int k){ return n*64 + (k ^ ((n & 7) << 3)); }
__device__ __forceinline__ int swz32(int n, int k){ return n*32 + (k ^ ((n & 6) << 2)); }
__device__ __forceinline__ int swz16(int n, int k){ return n*16 + (k ^ ((n & 4) << 1)); }

// stage W[K][N] f32 -> smem [n][k-swizzled] bf16 hi/lo
template<int KW>  // KW = halves per row: 64, 32, or 16
__device__ __forceinline__ void stageW_s(const float* __restrict__ g, char* smc,
                                         int hOff, int lOff, int K, int N, int tid){
    const float4* g4 = (const float4*)g;
    __nv_bfloat16* H = (__nv_bfloat16*)(smc + hOff);
    __nv_bfloat16* L = (__nv_bfloat16*)(smc + lOff);
    const int tot = (K*N) >> 2;
    for (int i = tid; i < tot; i += NTHR) {
        float4 w = __ldg(g4 + i);
        int k = i / (N >> 2);
        int n0 = (i % (N >> 2)) << 2;
        float vv[4] = {w.x, w.y, w.z, w.w};
        #pragma unroll
        for (int c = 0; c < 4; c++) {
            float v = vv[c];
            __nv_bfloat16 h = __float2bfloat16(v);
            __nv_bfloat16 l = __float2bfloat16(v - __bfloat162float(h));
            const int nn = n0 + c;
            const int idx = (KW == 64) ? swz64(nn, k) : (KW == 32) ? swz32(nn, k) : swz16(nn, k);
            H[idx] = h;
            L[idx] = l;
        }
    }
}

// one MMA layer: KS k-steps of 16, NT n-tiles of 8; two m-tiles (32 points).
template<int KS, int NT, bool RELU, bool UAL, int KW>
__device__ __forceinline__ void layerM(const char* smc, int hOff, int lOff,
                                       const float* bias,
                                       uint32_t ah[2][KS][4], uint32_t al[2][KS][4],
                                       float C[2][NT][4], int lane){
    const int t = lane & 3, u = lane >> 2;
    #pragma unroll
    for (int j = 0; j < NT; j++){
        float2 bb = *(const float2*)(bias + 8*j + 2*t);
        #pragma unroll
        for (int mt = 0; mt < 2; mt++){
            C[mt][j][0]=bb.x; C[mt][j][1]=bb.y; C[mt][j][2]=bb.x; C[mt][j][3]=bb.y;
        }
        #pragma unroll
        for (int s = 0; s < KS; s++){
            const int row = 8*j + u;
            const int k0 = 16*s + 2*t;
            int i0, i1;
            if (KW == 64)      { i0 = swz64(row, k0); i1 = swz64(row, k0 + 8); }
            else if (KW == 32) { i0 = swz32(row, k0); i1 = swz32(row, k0 + 8); }
            else               { i0 = swz16(row, k0); i1 = swz16(row, k0 + 8); }
            uint32_t bh0 = *(const uint32_t*)(smc + hOff + i0*2);
            uint32_t bh1 = *(const uint32_t*)(smc + hOff + i1*2);
            uint32_t bl0 = *(const uint32_t*)(smc + lOff + i0*2);
            uint32_t bl1 = *(const uint32_t*)(smc + lOff + i1*2);
            #pragma unroll
            for (int mt = 0; mt < 2; mt++){
                mmab(C[mt][j], ah[mt][s], bh0, bh1);
                if (UAL) mmab(C[mt][j], al[mt][s], bh0, bh1);
                mmab(C[mt][j], ah[mt][s], bl0, bl1);
            }
        }
        if (RELU){
            #pragma unroll
            for (int mt = 0; mt < 2; mt++)
                #pragma unroll
                for (int q = 0; q < 4; q++) C[mt][j][q] = fmaxf(C[mt][j][q], 0.f);
        }
    }
}

template<int KSN, int NTS>
__device__ __forceinline__ void convA(const float C[2][NTS][4],
                                      uint32_t ah[2][KSN][4], uint32_t al[2][KSN][4]){
    #pragma unroll
    for (int mt = 0; mt < 2; mt++)
        #pragma unroll
        for (int s = 0; s < KSN; s++){
            const float* c0 = C[mt][2*s];
            const float* c1 = C[mt][2*s+1];
            uint32_t h0 = pk(c0[0], c0[1]);
            uint32_t h1 = pk(c0[2], c0[3]);
            uint32_t h2 = pk(c1[0], c1[1]);
            uint32_t h3 = pk(c1[2], c1[3]);
            ah[mt][s][0]=h0; ah[mt][s][1]=h1; ah[mt][s][2]=h2; ah[mt][s][3]=h3;
            al[mt][s][0] = pk(c0[0]-blo(h0), c0[1]-bhi(h0));
            al[mt][s][1] = pk(c0[2]-blo(h1), c0[3]-bhi(h1));
            al[mt][s][2] = pk(c1[0]-blo(h2), c1[1]-bhi(h2));
            al[mt][s][3] = pk(c1[2]-blo(h3), c1[3]-bhi(h3));
        }
}

__device__ __forceinline__ float sg(float x){ return 1.f/(1.f + expf(-x)); }

// ACT addressing: word w of row r (0..31 within warp), perm keeps LDS conflict-free
__device__ __forceinline__ int act_idx(int warp, int r, int w){
    return warp*512 + r*16 + (w ^ ((r & 6) << 1));
}

extern "C" __global__ void __launch_bounds__(NTHR, 3)
nerf_mma(const float* __restrict__ gx, const float* __restrict__ gtab,
         const float* __restrict__ dw1, const float* __restrict__ db1,
         const float* __restrict__ dw2, const float* __restrict__ db2,
         const float* __restrict__ dw3, const float* __restrict__ db3,
         const float* __restrict__ cw1, const float* __restrict__ cb1,
         const float* __restrict__ cw2, const float* __restrict__ cb2,
         const float* __restrict__ cw3, const float* __restrict__ cb3,
         const float* __restrict__ cw4, const float* __restrict__ cb4,
         float* __restrict__ out, int n)
{
    extern __shared__ char smc[];
    const int tid = threadIdx.x;
    const int lane = tid & 31, warp = tid >> 5;
    const int t = lane & 3, u = lane >> 2;
    const int gbase = blockIdx.x * NPTS;

    // ---- stage all weights (swizzled, bf16 hi/lo) ----
    stageW_s<32>(dw1, smc, WD1H, WD1L, 32, 64, tid);
    stageW_s<64>(dw2, smc, WD2H, WD2L, 64, 64, tid);
    stageW_s<64>(dw3, smc, WD3H, WD3L, 64, 16, tid);
    stageW_s<16>(cw1, smc, WC1H, WC1L, 16, 64, tid);
    stageW_s<64>(cw2, smc, WC2H, WC2L, 64, 64, tid);
    stageW_s<64>(cw3, smc, WC3H, WC3L, 64, 64, tid);
    // head weights: rows 0..2 only (rows 3..7 garbage -> discarded outputs)
    if (tid < 64) {
        __nv_bfloat16* H = (__nv_bfloat16*)(smc + WHDH);
        __nv_bfloat16* L = (__nv_bfloat16*)(smc + WHDL);
        #pragma unroll
        for (int c = 0; c < 3; c++) {
            float v = __ldg(&cw4[tid*3 + c]);
            __nv_bfloat16 h = __float2bfloat16(v);
            const int idx = swz64(c, tid);
            H[idx] = h;
            L[idx] = __float2bfloat16(v - __bfloat162float(h));
        }
    }
    {
        float* bs = (float*)(smc + BIASO);
        if (tid < 64) {
            bs[DB1 + tid] = __ldg(db1 + tid);
            bs[DB2 + tid] = __ldg(db2 + tid);
            bs[CB1 + tid] = __ldg(cb1 + tid);
            bs[CB2 + tid] = __ldg(cb2 + tid);
            bs[CB3 + tid] = __ldg(cb3 + tid);
            if (tid < 16) bs[DB3 + tid] = __ldg(db3 + tid);
            if (tid < 8)  bs[HB + tid] = (tid < 3) ? __ldg(cb4 + tid) : 0.f;
        }
    }

    // ---- hash-grid encode (thread p encodes point p, all levels) ----
    {
        const int gp = gbase + tid;
        const bool valid = gp < n;
        float px = 0.f, py = 0.f, pz = 0.f;
        if (valid) { px = gx[3*gp]; py = gx[3*gp+1]; pz = gx[3*gp+2]; }
        const float ux = px*0.5f + 0.5f, uy = py*0.5f + 0.5f, uz = pz*0.5f + 0.5f;

        uint32_t feat[16];
        #pragma unroll
        for (int l = 0; l < 16; l++) {
            const int res = RESV[l];
            const bool dense = (l < 5);
            float f0 = 0.f, f1 = 0.f;
            if (valid) {
                const float rm1 = (float)(res - 1);
                float qx = ux*rm1, qy = uy*rm1, qz = uz*rm1;
                int cx = (int)floorf(qx); cx = max(0, min(cx, res-2));
                int cy = (int)floorf(qy); cy = max(0, min(cy, res-2));
                int cz = (int)floorf(qz); cz = max(0, min(cz, res-2));
                float wx = qx-(float)cx, wy = qy-(float)cy, wz = qz-(float)cz;
                float mx = 1.f-wx, my = 1.f-wy, mz = 1.f-wz;

                if (dense) {
                    const float4* dt = g_dense + DOFF[l];
                    #pragma unroll
                    for (int c4 = 0; c4 < 4; c4++) {
                        const int oy = (c4 >> 1) & 1, oz = c4 & 1;
                        const float wyz = (oy?wy:my)*(oz?wz:mz);
                        const int idx = cx + res*((cy+oy) + res*(cz+oz));
                        const float4 e = __ldg(dt + idx);
                        f0 += wyz*(mx*e.x + wx*e.z);
                        f1 += wyz*(mx*e.y + wx*e.w);
                    }
                } else {
                    const float2* tab = (const float2*)gtab + ((size_t)l << 16);
                    const float4* tab4 = (const float4*)gtab + ((size_t)l << 15);
                    const bool cxe = ((cx & 1) == 0);
                    #pragma unroll
                    for (int c4 = 0; c4 < 4; c4++) {
                        const int oy = (c4 >> 1) & 1, oz = c4 & 1;
                        const float wyz = (oy?wy:my)*(oz?wz:mz);
                        const unsigned hyz = (unsigned)(cy+oy)*2654435761u
                                           ^ (unsigned)(cz+oz)*805459861u;
                        const unsigned i0 = ((unsigned)cx ^ hyz) & 65535u;
                        float e0x, e0y, e1x, e1y;
                        if (cxe) {
                            const float4 e = __ldg(tab4 + (i0 >> 1));
                            const bool lo = ((i0 & 1u) == 0u);
                            e0x = lo ? e.x : e.z;  e0y = lo ? e.y : e.w;
                            e1x = lo ? e.z : e.x;  e1y = lo ? e.w : e.y;
                        } else {
                            const unsigned i1 = ((unsigned)(cx+1) ^ hyz) & 65535u;
                            const float2 a = __ldg(tab + i0);
                            const float2 b = __ldg(tab + i1);
                            e0x = a.x; e0y = a.y; e1x = b.x; e1y = b.y;
                        }
                        f0 += wyz*(mx*e0x + wx*e1x);
                        f1 += wyz*(mx*e0y + wx*e1y);
                    }
                }
            }
            feat[l] = pk(f0, f1);
        }
        // store as 4 x STS.128 with 4-aligned XOR perm
        uint4* A4 = (uint4*)((uint32_t*)(smc + ACTO));
        const int g = (lane >> 1) & 3;
        const int base4 = (warp*512 + lane*16) >> 2;   // uint4 index
        #pragma unroll
        for (int a = 0; a < 4; a++) {
            A4[base4 + (a ^ g)] =
                make_uint4(feat[4*a], feat[4*a+1], feat[4*a+2], feat[4*a+3]);
        }
    }
    __syncthreads();

    const float* bs = (const float*)(smc + BIASO);
    uint32_t ah[2][4][4], al[2][4][4];
    float Ca[2][8][4], Cb[2][8][4];

    // ---- d1: 32 -> 64 relu (A from ACT, hi only; W hi/lo) ----
    {
        const uint32_t* act = (const uint32_t*)(smc + ACTO);
        uint32_t ah1[2][2][4];
        #pragma unroll
        for (int mt = 0; mt < 2; mt++)
            #pragma unroll
            for (int s = 0; s < 2; s++) {
                ah1[mt][s][0] = act[act_idx(warp, mt*16 + u,     8*s + t)];
                ah1[mt][s][1] = act[act_idx(warp, mt*16 + u + 8, 8*s + t)];
                ah1[mt][s][2] = act[act_idx(warp, mt*16 + u,     8*s + 4 + t)];
                ah1[mt][s][3] = act[act_idx(warp, mt*16 + u + 8, 8*s + 4 + t)];
            }
        layerM<2,8,true,false,32>(smc, WD1H, WD1L, bs + DB1, ah1, ah1, Ca, lane);
    }

    // ---- d2: 64 -> 64 relu ----
    convA<4,8>(Ca, ah, al);
    layerM<4,8,true,true,64>(smc, WD2H, WD2L, bs + DB2, ah, al, Cb, lane);

    // ---- d3: 64 -> 16 (no relu) + sigma ----
    float Cd[2][2][4];
    convA<4,8>(Cb, ah, al);
    layerM<4,2,false,true,64>(smc, WD3H, WD3L, bs + DB3, ah, al, Cd, lane);
    if (t == 0) {
        #pragma unroll
        for (int mt = 0; mt < 2; mt++) {
            int g = gbase + warp*32 + mt*16 + u;
            if (g < n)     out[g]     = expf(Cd[mt][0][0]);
            if (g + 8 < n) out[g + 8] = expf(Cd[mt][0][2]);
        }
    }

    // ---- c1: 16 -> 64 relu ----
    {
        uint32_t ah1b[2][1][4], al1b[2][1][4];
        convA<1,2>(Cd, ah1b, al1b);
        layerM<1,8,true,true,16>(smc, WC1H, WC1L, bs + CB1, ah1b, al1b, Ca, lane);
    }

    // ---- c2: 64 -> 64 relu ----
    convA<4,8>(Ca, ah, al);
    layerM<4,8,true,true,64>(smc, WC2H, WC2L, bs + CB2, ah, al, Cb, lane);

    // ---- c3: 64 -> 64 relu ----
    convA<4,8>(Cb, ah, al);
    layerM<4,8,true,true,64>(smc, WC3H, WC3L, bs + CB3, ah, al, Ca, lane);

    // ---- color head: 64 -> 3 (rows 3..7 garbage, discarded), sigmoid ----
    {
        float Ch[2][1][4];
        convA<4,8>(Ca, ah, al);
        layerM<4,1,false,true,64>(smc, WHDH, WHDL, bs + HB, ah, al, Ch, lane);
        #pragma unroll
        for (int mt = 0; mt < 2; mt++) {
            int g0 = gbase + warp*32 + mt*16 + u;
            int g1 = g0 + 8;
            if (t == 0) {
                if (g0 < n) {
                    out[n + 3*g0 + 0] = sg(Ch[mt][0][0]);
                    out[n + 3*g0 + 1] = sg(Ch[mt][0][1]);
                }
                if (g1 < n) {
                    out[n + 3*g1 + 0] = sg(Ch[mt][0][2]);
                    out[n + 3*g1 + 1] = sg(Ch[mt][0][3]);
                }
            } else if (t == 1) {
                if (g0 < n) out[n + 3*g0 + 2] = sg(Ch[mt][0][0]);
                if (g1 < n) out[n + 3*g1 + 2] = sg(Ch[mt][0][2]);
            }
        }
    }
}

extern "C" void kernel_launch(void* const* d_in, const int* in_sizes, int n_in,
                              void* d_out, int out_size)
{
    const int n = in_sizes[0] / 3;
    static int cfg = 0;
    if (!cfg) {
        cudaFuncSetAttribute(nerf_mma, cudaFuncAttributeMaxDynamicSharedMemorySize, SMEMB);
        cfg = 1;
    }
    const float* gtab = (const float*)d_in[1];
    prep_dense<<<(DTOT + 255)/256, 256>>>(gtab);
    const int blocks = (n + NPTS - 1) / NPTS;
    nerf_mma<<<blocks, NTHR, SMEMB>>>(
        (const float*)d_in[0], gtab,
        (const float*)d_in[2], (const float*)d_in[3],
        (const float*)d_in[4], (const float*)d_in[5],
        (const float*)d_in[6], (const float*)d_in[7],
        (const float*)d_in[8], (const float*)d_in[9],
        (const float*)d_in[10], (const float*)d_in[11],
        (const float*)d_in[12], (const float*)d_in[13],
        (const float*)d_in[14], (const float*)d_in[15],
        (float*)d_out, n);
}

// round 16
// speedup vs baseline: 1.6097x; 1.6097x over previous
#include <cuda_runtime.h>
#include <cuda_bf16.h>
#include <math.h>
#include <stdint.h>

#define NPTS 128
#define NTHR 128

// ---- smem byte offsets (all swizzled, zero padding) ----
#define WD1H 0        // 64 rows x 32 halves = 4096
#define WD1L 4096
#define WD2H 8192     // 64 x 64 = 8192
#define WD2L 16384
#define WD3H 24576    // 16 x 64 = 2048
#define WD3L 26624
#define WC1H 28672    // 64 x 16 = 2048
#define WC1L 30720
#define WC2H 32768
#define WC2L 40960
#define WC3H 49152
#define WC3L 57344
#define WHDH 65536    // 8 x 64 = 1024
#define WHDL 66560
#define BIASO 67584   // floats, 1408B
#define ACT0  68992   // ping: 4 warps x 32 x 16 words x 4B = 8192
#define ACT1  77184   // pong
#define SMEMB 85376
#define DB1 0
#define DB2 64
#define DB3 128
#define CB1 144
#define CB2 208
#define CB3 272
#define HB  336

__device__ constexpr int RESV[16] = {16,20,25,32,40,50,64,80,101,128,161,203,256,322,406,512};

// pair-packed dense tables (levels 0..4)
#define DTOT 124489
__device__ float4 g_dense[DTOT];
__device__ constexpr int DOFF[5] = {0, 4096, 12096, 27721, 60489};

__global__ void __launch_bounds__(256) prep_dense(const float* __restrict__ gtab)
{
    int i = blockIdx.x * 256 + threadIdx.x;
    if (i >= DTOT) return;
    int l, off, sz;
    if      (i < 4096)  { l=0; off=0;     sz=4096;  }
    else if (i < 12096) { l=1; off=4096;  sz=8000;  }
    else if (i < 27721) { l=2; off=12096; sz=15625; }
    else if (i < 60489) { l=3; off=27721; sz=32768; }
    else                { l=4; off=60489; sz=64000; }
    int j = i - off;
    const float2* tab = (const float2*)gtab + ((size_t)l << 16);
    float2 a = tab[j];
    float2 b = tab[j + 1 < sz ? j + 1 : j];
    g_dense[i] = make_float4(a.x, a.y, b.x, b.y);
}

__device__ __forceinline__ uint32_t pk(float lo, float hi){
    uint32_t r; asm("cvt.rn.bf16x2.f32 %0, %1, %2;" : "=r"(r) : "f"(hi), "f"(lo)); return r;
}
__device__ __forceinline__ float blo(uint32_t v){ return __uint_as_float(v << 16); }
__device__ __forceinline__ float bhi(uint32_t v){ return __uint_as_float(v & 0xFFFF0000u); }

__device__ __forceinline__ void mmab(float* c, const uint32_t* a, uint32_t b0, uint32_t b1){
    asm volatile("mma.sync.aligned.m16n8k16.row.col.f32.bf16.bf16.f32 "
        "{%0,%1,%2,%3}, {%4,%5,%6,%7}, {%8,%9}, {%0,%1,%2,%3};"
        : "+f"(c[0]), "+f"(c[1]), "+f"(c[2]), "+f"(c[3])
        : "r"(a[0]), "r"(a[1]), "r"(a[2]), "r"(a[3]), "r"(b0), "r"(b1));
}

// swizzle helpers: k' index within a row of KW halves
__device__ __forceinline__ int swz64(int n, int k){ return n*64 + (k ^ ((n & 7) << 3)); }
__device__ __forceinline__ int swz32(int n, int k){ return n*32 + (k ^ ((n & 6) << 2)); }
__device__ __forceinline__ int swz16(int n, int k){ return n*16 + (k ^ ((n & 4) << 1)); }

// stage W[K][N] f32 -> smem [n][k-swizzled] bf16 hi/lo
template<int KW>
__device__ __forceinline__ void stageW_s(const float* __restrict__ g, char* smc,
                                         int hOff, int lOff, int K, int N, int tid){
    const float4* g4 = (const float4*)g;
    __nv_bfloat16* H = (__nv_bfloat16*)(smc + hOff);
    __nv_bfloat16* L = (__nv_bfloat16*)(smc + lOff);
    const int tot = (K*N) >> 2;
    for (int i = tid; i < tot; i += NTHR) {
        float4 w = __ldg(g4 + i);
        int k = i / (N >> 2);
        int n0 = (i % (N >> 2)) << 2;
        float vv[4] = {w.x, w.y, w.z, w.w};
        #pragma unroll
        for (int c = 0; c < 4; c++) {
            float v = vv[c];
            __nv_bfloat16 h = __float2bfloat16(v);
            __nv_bfloat16 l = __float2bfloat16(v - __bfloat162float(h));
            const int nn = n0 + c;
            const int idx = (KW == 64) ? swz64(nn, k) : (KW == 32) ? swz32(nn, k) : swz16(nn, k);
            H[idx] = h;
            L[idx] = l;
        }
    }
}

// one MMA layer: KS k-steps of 16, NT n-tiles of 8; two m-tiles (32 points).
template<int KS, int NT, bool RELU, bool UAL, int KW>
__device__ __forceinline__ void layerM(const char* smc, int hOff, int lOff,
                                       const float* bias,
                                       uint32_t ah[2][KS][4], uint32_t al[2][KS][4],
                                       float C[2][NT][4], int lane){
    const int t = lane & 3, u = lane >> 2;
    #pragma unroll
    for (int j = 0; j < NT; j++){
        float2 bb = *(const float2*)(bias + 8*j + 2*t);
        #pragma unroll
        for (int mt = 0; mt < 2; mt++){
            C[mt][j][0]=bb.x; C[mt][j][1]=bb.y; C[mt][j][2]=bb.x; C[mt][j][3]=bb.y;
        }
        #pragma unroll
        for (int s = 0; s < KS; s++){
            const int row = 8*j + u;
            const int k0 = 16*s + 2*t;
            int i0, i1;
            if (KW == 64)      { i0 = swz64(row, k0); i1 = swz64(row, k0 + 8); }
            else if (KW == 32) { i0 = swz32(row, k0); i1 = swz32(row, k0 + 8); }
            else               { i0 = swz16(row, k0); i1 = swz16(row, k0 + 8); }
            uint32_t bh0 = *(const uint32_t*)(smc + hOff + i0*2);
            uint32_t bh1 = *(const uint32_t*)(smc + hOff + i1*2);
            uint32_t bl0 = *(const uint32_t*)(smc + lOff + i0*2);
            uint32_t bl1 = *(const uint32_t*)(smc + lOff + i1*2);
            #pragma unroll
            for (int mt = 0; mt < 2; mt++){
                mmab(C[mt][j], ah[mt][s], bh0, bh1);
                if (UAL) mmab(C[mt][j], al[mt][s], bh0, bh1);
                mmab(C[mt][j], ah[mt][s], bl0, bl1);
            }
        }
        if (RELU){
            #pragma unroll
            for (int mt = 0; mt < 2; mt++)
                #pragma unroll
                for (int q = 0; q < 4; q++) C[mt][j][q] = fmaxf(C[mt][j][q], 0.f);
        }
    }
}

template<int KSN, int NTS>
__device__ __forceinline__ void convA(const float C[2][NTS][4],
                                      uint32_t ah[2][KSN][4], uint32_t al[2][KSN][4]){
    #pragma unroll
    for (int mt = 0; mt < 2; mt++)
        #pragma unroll
        for (int s = 0; s < KSN; s++){
            const float* c0 = C[mt][2*s];
            const float* c1 = C[mt][2*s+1];
            uint32_t h0 = pk(c0[0], c0[1]);
            uint32_t h1 = pk(c0[2], c0[3]);
            uint32_t h2 = pk(c1[0], c1[1]);
            uint32_t h3 = pk(c1[2], c1[3]);
            ah[mt][s][0]=h0; ah[mt][s][1]=h1; ah[mt][s][2]=h2; ah[mt][s][3]=h3;
            al[mt][s][0] = pk(c0[0]-blo(h0), c0[1]-bhi(h0));
            al[mt][s][1] = pk(c0[2]-blo(h1), c0[3]-bhi(h1));
            al[mt][s][2] = pk(c1[0]-blo(h2), c1[1]-bhi(h2));
            al[mt][s][3] = pk(c1[2]-blo(h3), c1[3]-bhi(h3));
        }
}

__device__ __forceinline__ float sg(float x){ return 1.f/(1.f + expf(-x)); }

// ACT addressing within a buffer: word w of row r, XOR perm, conflict-free
__device__ __forceinline__ int act_idx(int warp, int r, int w){
    return warp*512 + r*16 + (w ^ ((r & 6) << 1));
}

extern "C" __global__ void __launch_bounds__(NTHR)
nerf_mma(const float* __restrict__ gx, const float* __restrict__ gtab,
         const float* __restrict__ dw1, const float* __restrict__ db1,
         const float* __restrict__ dw2, const float* __restrict__ db2,
         const float* __restrict__ dw3, const float* __restrict__ db3,
         const float* __restrict__ cw1, const float* __restrict__ cb1,
         const float* __restrict__ cw2, const float* __restrict__ cb2,
         const float* __restrict__ cw3, const float* __restrict__ cb3,
         const float* __restrict__ cw4, const float* __restrict__ cb4,
         float* __restrict__ out, int n, int ntiles)
{
    extern __shared__ char smc[];
    const int tid = threadIdx.x;
    const int lane = tid & 31, warp = tid >> 5;
    const int t = lane & 3, u = lane >> 2;

    // ---- stage all weights ONCE per persistent CTA ----
    stageW_s<32>(dw1, smc, WD1H, WD1L, 32, 64, tid);
    stageW_s<64>(dw2, smc, WD2H, WD2L, 64, 64, tid);
    stageW_s<64>(dw3, smc, WD3H, WD3L, 64, 16, tid);
    stageW_s<16>(cw1, smc, WC1H, WC1L, 16, 64, tid);
    stageW_s<64>(cw2, smc, WC2H, WC2L, 64, 64, tid);
    stageW_s<64>(cw3, smc, WC3H, WC3L, 64, 64, tid);
    for (int i = tid; i < 512; i += NTHR) ((uint32_t*)(smc + WHDH))[i] = 0u;
    __syncthreads();   // zero-fill visible before cw4 scatter
    if (tid < 64) {
        __nv_bfloat16* H = (__nv_bfloat16*)(smc + WHDH);
        __nv_bfloat16* L = (__nv_bfloat16*)(smc + WHDL);
        #pragma unroll
        for (int c = 0; c < 3; c++) {
            float v = __ldg(&cw4[tid*3 + c]);
            __nv_bfloat16 h = __float2bfloat16(v);
            const int idx = swz64(c, tid);
            H[idx] = h;
            L[idx] = __float2bfloat16(v - __bfloat162float(h));
        }
    }
    {
        float* bsw = (float*)(smc + BIASO);
        if (tid < 64) {
            bsw[DB1 + tid] = __ldg(db1 + tid);
            bsw[DB2 + tid] = __ldg(db2 + tid);
            bsw[CB1 + tid] = __ldg(cb1 + tid);
            bsw[CB2 + tid] = __ldg(cb2 + tid);
            bsw[CB3 + tid] = __ldg(cb3 + tid);
            if (tid < 16) bsw[DB3 + tid] = __ldg(db3 + tid);
            if (tid < 8)  bsw[HB + tid] = (tid < 3) ? __ldg(cb4 + tid) : 0.f;
        }
    }
    __syncthreads();   // weights + biases ready for all iterations

    const float* bs = (const float*)(smc + BIASO);
    int par = 0;

    for (int tile = blockIdx.x; tile < ntiles; tile += gridDim.x, par ^= 1) {
        const int gbase = tile * NPTS;
        const int actoff = par ? ACT1 : ACT0;

        // ---- hash-grid encode (thread p encodes point p, all levels) ----
        {
            const int gp = gbase + tid;
            const bool valid = gp < n;
            float px = 0.f, py = 0.f, pz = 0.f;
            if (valid) { px = gx[3*gp]; py = gx[3*gp+1]; pz = gx[3*gp+2]; }
            const float ux = px*0.5f + 0.5f, uy = py*0.5f + 0.5f, uz = pz*0.5f + 0.5f;

            uint32_t feat[16];
            #pragma unroll
            for (int l = 0; l < 16; l++) {
                const int res = RESV[l];
                const bool dense = (l < 5);
                float f0 = 0.f, f1 = 0.f;
                if (valid) {
                    const float rm1 = (float)(res - 1);
                    float qx = ux*rm1, qy = uy*rm1, qz = uz*rm1;
                    int cx = (int)floorf(qx); cx = max(0, min(cx, res-2));
                    int cy = (int)floorf(qy); cy = max(0, min(cy, res-2));
                    int cz = (int)floorf(qz); cz = max(0, min(cz, res-2));
                    float wx = qx-(float)cx, wy = qy-(float)cy, wz = qz-(float)cz;
                    float mx = 1.f-wx, my = 1.f-wy, mz = 1.f-wz;

                    if (dense) {
                        const float4* dt = g_dense + DOFF[l];
                        #pragma unroll
                        for (int c4 = 0; c4 < 4; c4++) {
                            const int oy = (c4 >> 1) & 1, oz = c4 & 1;
                            const float wyz = (oy?wy:my)*(oz?wz:mz);
                            const int idx = cx + res*((cy+oy) + res*(cz+oz));
                            const float4 e = __ldg(dt + idx);
                            f0 += wyz*(mx*e.x + wx*e.z);
                            f1 += wyz*(mx*e.y + wx*e.w);
                        }
                    } else {
                        const float2* tab = (const float2*)gtab + ((size_t)l << 16);
                        const float4* tab4 = (const float4*)gtab + ((size_t)l << 15);
                        const bool cxe = ((cx & 1) == 0);
                        #pragma unroll
                        for (int c4 = 0; c4 < 4; c4++) {
                            const int oy = (c4 >> 1) & 1, oz = c4 & 1;
                            const float wyz = (oy?wy:my)*(oz?wz:mz);
                            const unsigned hyz = (unsigned)(cy+oy)*2654435761u
                                               ^ (unsigned)(cz+oz)*805459861u;
                            const unsigned i0 = ((unsigned)cx ^ hyz) & 65535u;
                            float e0x, e0y, e1x, e1y;
                            if (cxe) {
                                const float4 e = __ldg(tab4 + (i0 >> 1));
                                const bool lo = ((i0 & 1u) == 0u);
                                e0x = lo ? e.x : e.z;  e0y = lo ? e.y : e.w;
                                e1x = lo ? e.z : e.x;  e1y = lo ? e.w : e.y;
                            } else {
                                const unsigned i1 = ((unsigned)(cx+1) ^ hyz) & 65535u;
                                const float2 a = __ldg(tab + i0);
                                const float2 b = __ldg(tab + i1);
                                e0x = a.x; e0y = a.y; e1x = b.x; e1y = b.y;
                            }
                            f0 += wyz*(mx*e0x + wx*e1x);
                            f1 += wyz*(mx*e0y + wx*e1y);
                        }
                    }
                }
                feat[l] = pk(f0, f1);
            }
            // 4 x STS.128 with 4-aligned XOR perm
            uint4* A4 = (uint4*)((uint32_t*)(smc + actoff));
            const int g = (lane >> 1) & 3;
            const int base4 = (warp*512 + lane*16) >> 2;
            #pragma unroll
            for (int a = 0; a < 4; a++) {
                A4[base4 + (a ^ g)] =
                    make_uint4(feat[4*a], feat[4*a+1], feat[4*a+2], feat[4*a+3]);
            }
        }
        __syncthreads();   // ACT(par) ready; also guards next iter's other-buffer WAR

        uint32_t ah[2][4][4], al[2][4][4];
        float Ca[2][8][4], Cb[2][8][4];

        // ---- d1: 32 -> 64 relu ----
        {
            const uint32_t* act = (const uint32_t*)(smc + actoff);
            uint32_t ah1[2][2][4];
            #pragma unroll
            for (int mt = 0; mt < 2; mt++)
                #pragma unroll
                for (int s = 0; s < 2; s++) {
                    ah1[mt][s][0] = act[act_idx(warp, mt*16 + u,     8*s + t)];
                    ah1[mt][s][1] = act[act_idx(warp, mt*16 + u + 8, 8*s + t)];
                    ah1[mt][s][2] = act[act_idx(warp, mt*16 + u,     8*s + 4 + t)];
                    ah1[mt][s][3] = act[act_idx(warp, mt*16 + u + 8, 8*s + 4 + t)];
                }
            layerM<2,8,true,false,32>(smc, WD1H, WD1L, bs + DB1, ah1, ah1, Ca, lane);
        }

        // ---- d2: 64 -> 64 relu ----
        convA<4,8>(Ca, ah, al);
        layerM<4,8,true,true,64>(smc, WD2H, WD2L, bs + DB2, ah, al, Cb, lane);

        // ---- d3: 64 -> 16 (no relu) + sigma ----
        float Cd[2][2][4];
        convA<4,8>(Cb, ah, al);
        layerM<4,2,false,true,64>(smc, WD3H, WD3L, bs + DB3, ah, al, Cd, lane);
        if (t == 0) {
            #pragma unroll
            for (int mt = 0; mt < 2; mt++) {
                int g = gbase + warp*32 + mt*16 + u;
                if (g < n)     out[g]     = expf(Cd[mt][0][0]);
                if (g + 8 < n) out[g + 8] = expf(Cd[mt][0][2]);
            }
        }

        // ---- c1: 16 -> 64 relu ----
        {
            uint32_t ah1b[2][1][4], al1b[2][1][4];
            convA<1,2>(Cd, ah1b, al1b);
            layerM<1,8,true,true,16>(smc, WC1H, WC1L, bs + CB1, ah1b, al1b, Ca, lane);
        }

        // ---- c2: 64 -> 64 relu ----
        convA<4,8>(Ca, ah, al);
        layerM<4,8,true,true,64>(smc, WC2H, WC2L, bs + CB2, ah, al, Cb, lane);

        // ---- c3: 64 -> 64 relu ----
        convA<4,8>(Cb, ah, al);
        layerM<4,8,true,true,64>(smc, WC3H, WC3L, bs + CB3, ah, al, Ca, lane);

        // ---- color head: 64 -> 3(pad 8), sigmoid ----
        {
            float Ch[2][1][4];
            convA<4,8>(Ca, ah, al);
            layerM<4,1,false,true,64>(smc, WHDH, WHDL, bs + HB, ah, al, Ch, lane);
            #pragma unroll
            for (int mt = 0; mt < 2; mt++) {
                int g0 = gbase + warp*32 + mt*16 + u;
                int g1 = g0 + 8;
                if (t == 0) {
                    if (g0 < n) {
                        out[n + 3*g0 + 0] = sg(Ch[mt][0][0]);
                        out[n + 3*g0 + 1] = sg(Ch[mt][0][1]);
                    }
                    if (g1 < n) {
                        out[n + 3*g1 + 0] = sg(Ch[mt][0][2]);
                        out[n + 3*g1 + 1] = sg(Ch[mt][0][3]);
                    }
                } else if (t == 1) {
                    if (g0 < n) out[n + 3*g0 + 2] = sg(Ch[mt][0][0]);
                    if (g1 < n) out[n + 3*g1 + 2] = sg(Ch[mt][0][2]);
                }
            }
        }
    }
}

extern "C" void kernel_launch(void* const* d_in, const int* in_sizes, int n_in,
                              void* d_out, int out_size)
{
    const int n = in_sizes[0] / 3;
    static int cfg = 0;
    if (!cfg) {
        cudaFuncSetAttribute(nerf_mma, cudaFuncAttributeMaxDynamicSharedMemorySize, SMEMB);
        cfg = 1;
    }
    const float* gtab = (const float*)d_in[1];
    prep_dense<<<(DTOT + 255)/256, 256>>>(gtab);
    const int ntiles = (n + NPTS - 1) / NPTS;
    const int blocks = ntiles < 296 ? ntiles : 296;   // 2 persistent CTAs per SM
    nerf_mma<<<blocks, NTHR, SMEMB>>>(
        (const float*)d_in[0], gtab,
        (const float*)d_in[2], (const float*)d_in[3],
        (const float*)d_in[4], (const float*)d_in[5],
        (const float*)d_in[6], (const float*)d_in[7],
        (const float*)d_in[8], (const float*)d_in[9],
        (const float*)d_in[10], (const float*)d_in[11],
        (const float*)d_in[12], (const float*)d_in[13],
        (const float*)d_in[14], (const float*)d_in[15],
        (float*)d_out, n, ntiles);
}